// round 14
// baseline (speedup 1.0000x reference)
#include <cuda_runtime.h>
#include <cuda_fp16.h>
#include <cstdint>

#define NV   200000
#define NPAD 200064
#define TIL  1563
#define KOFF 27
#define CA   64
#define CB   128
#define NBLK 256
#define EPSF 1e-5f

// ---------------- device scratch ----------------
__device__ __half g_f0h[(NV + 1) * CA];
__device__ __half g_h1h[(NV + 1) * CB];
__device__ __half g_temp[(size_t)KOFF * NPAD * 128];  // fp16 partial rows
__device__ int    g_p2t[NPAD * 32];                   // per-output slot+1 per k
__device__ __half g_base2h[(size_t)NPAD * 128];       // skip GEMM out (fp16)
__device__ __half g_w1h[KOFF * CB * CA];
__device__ __half g_w2h[KOFF * CB * CB];
__device__ float  g_tb1f[KOFF * 128];
__device__ float  g_tb2f[KOFF * 128];
__device__ __half g_wnh[CB * 64];
__device__ float  g_psum[NBLK * CB];
__device__ float  g_psq [NBLK * CB];
__device__ float  g_sc[2][CB];
__device__ float  g_sh[2][CB];

// ---------------- helpers ----------------
__device__ __forceinline__ uint32_t smem_u32(const void* p) {
    uint32_t a;
    asm("{ .reg .u64 t; cvta.to.shared.u64 t, %1; cvt.u32.u64 %0, t; }" : "=r"(a) : "l"(p));
    return a;
}
__device__ __forceinline__ void cpa16(uint32_t s, const void* g) {
    asm volatile("cp.async.cg.shared.global [%0], [%1], 16;" :: "r"(s), "l"(g));
}
__device__ __forceinline__ void cpa_commit() { asm volatile("cp.async.commit_group;" ::: "memory"); }
__device__ __forceinline__ void cpa_wait1()  { asm volatile("cp.async.wait_group 1;" ::: "memory"); }
__device__ __forceinline__ void cpa_wait0()  { asm volatile("cp.async.wait_group 0;" ::: "memory"); }
__device__ __forceinline__ void ldsm4(uint32_t* d, uint32_t addr) {
    asm volatile("ldmatrix.sync.aligned.m8n8.x4.shared.b16 {%0,%1,%2,%3}, [%4];"
                 : "=r"(d[0]), "=r"(d[1]), "=r"(d[2]), "=r"(d[3]) : "r"(addr));
}
__device__ __forceinline__ void mma16(float* c, const uint32_t* a, const uint32_t* b) {
    asm volatile(
        "mma.sync.aligned.m16n8k16.row.col.f32.f16.f16.f32 "
        "{%0,%1,%2,%3}, {%4,%5,%6,%7}, {%8,%9}, {%0,%1,%2,%3};"
        : "+f"(c[0]), "+f"(c[1]), "+f"(c[2]), "+f"(c[3])
        : "r"(a[0]), "r"(a[1]), "r"(a[2]), "r"(a[3]), "r"(b[0]), "r"(b[1]));
}
__device__ __forceinline__ void mma16h(uint32_t* c, const uint32_t* a, const uint32_t* b) {
    asm volatile(
        "mma.sync.aligned.m16n8k16.row.col.f16.f16.f16.f16 "
        "{%0,%1}, {%2,%3,%4,%5}, {%6,%7}, {%0,%1};"
        : "+r"(c[0]), "+r"(c[1])
        : "r"(a[0]), "r"(a[1]), "r"(a[2]), "r"(a[3]), "r"(b[0]), "r"(b[1]));
}
__device__ __forceinline__ void stcs32(void* p, uint32_t v) {
    asm volatile("st.global.cs.b32 [%0], %1;" :: "l"(p), "r"(v) : "memory");
}
__device__ __forceinline__ uint2 ldcs64(const void* p) {
    uint2 r;
    asm volatile("ld.global.cs.v2.b32 {%0,%1}, [%2];" : "=r"(r.x), "=r"(r.y) : "l"(p));
    return r;
}

// ---------------- BN stats: fp32 feats (+ zero p2t) ----------------
template <int C>
__global__ void k_bn_partial(const float* __restrict__ x) {
    const int tid = threadIdx.x;
    if (C == CA) {
        const int n4 = NPAD * 32 / 4;
        for (int i = blockIdx.x * 256 + tid; i < n4; i += NBLK * 256)
            ((int4*)g_p2t)[i] = make_int4(0, 0, 0, 0);
    }
    const int C4 = C / 4;
    float4 s = make_float4(0.f, 0.f, 0.f, 0.f);
    float4 q = make_float4(0.f, 0.f, 0.f, 0.f);
    const int tot = NV * C4;
    for (int i = blockIdx.x * 256 + tid; i < tot; i += NBLK * 256) {
        float4 v = ((const float4*)x)[i];
        s.x += v.x; s.y += v.y; s.z += v.z; s.w += v.w;
        q.x += v.x * v.x; q.y += v.y * v.y; q.z += v.z * v.z; q.w += v.w * v.w;
    }
    __shared__ float4 sh[256];
    sh[tid] = s;
    __syncthreads();
    if (tid < C4) {
        float4 a = sh[tid];
        for (int o = C4; o < 256; o += C4) {
            float4 b = sh[tid + o];
            a.x += b.x; a.y += b.y; a.z += b.z; a.w += b.w;
        }
        ((float4*)(g_psum + blockIdx.x * C))[tid] = a;
    }
    __syncthreads();
    sh[tid] = q;
    __syncthreads();
    if (tid < C4) {
        float4 a = sh[tid];
        for (int o = C4; o < 256; o += C4) {
            float4 b = sh[tid + o];
            a.x += b.x; a.y += b.y; a.z += b.z; a.w += b.w;
        }
        ((float4*)(g_psq + blockIdx.x * C))[tid] = a;
    }
}

template <int C, int IDX>
__global__ void k_bn_finalize(const float* __restrict__ gamma, const float* __restrict__ beta) {
    const int tid = threadIdx.x;   // blockDim = 4*C
    const int c = tid % C;
    const int qd = tid / C;
    float s = 0.f, s2 = 0.f;
    #pragma unroll 8
    for (int b = qd * (NBLK / 4); b < (qd + 1) * (NBLK / 4); ++b) {
        s  += g_psum[b * C + c];
        s2 += g_psq [b * C + c];
    }
    __shared__ float sha[4 * CB], shb[4 * CB];
    sha[tid] = s; shb[tid] = s2;
    __syncthreads();
    if (qd == 0) {
        s  = sha[c] + sha[C + c] + sha[2 * C + c] + sha[3 * C + c];
        s2 = shb[c] + shb[C + c] + shb[2 * C + c] + shb[3 * C + c];
        float mean = s / (float)NV;
        float var  = s2 / (float)NV - mean * mean;
        float a = rsqrtf(var + EPSF) * gamma[c];
        g_sc[IDX][c] = a;
        g_sh[IDX][c] = beta[c] - mean * a;
    }
}

// ---------------- prep1 ----------------
#define NB_F0  12500
#define NB_W1  864
#define NB_TBF 14
#define NB_MI  1
#define NB_MAP 21094
__global__ void k_prep1(const float* __restrict__ feats, const float* __restrict__ w1,
                        const int* __restrict__ sidx) {
    const int b = blockIdx.x;
    const int tid = threadIdx.x;
    if (b < NB_F0) {
        int i = b * 256 + tid;
        float4 v = ((const float4*)feats)[i];
        ((__half2*)g_f0h)[2 * i]     = __floats2half2_rn(v.x, v.y);
        ((__half2*)g_f0h)[2 * i + 1] = __floats2half2_rn(v.z, v.w);
    } else if (b < NB_F0 + NB_W1) {
        int i = (b - NB_F0) * 256 + tid;
        int k = i >> 13;
        int rem = i & 8191;
        int n = rem >> 6, c = rem & 63;
        g_w1h[i] = __float2half_rn(g_sc[0][c] * w1[(k * 64 + c) * 128 + n]);
    } else if (b < NB_F0 + NB_W1 + NB_TBF) {
        int i = (b - NB_F0 - NB_W1) * 256 + tid;
        if (i < KOFF * 128) {
            int k = i >> 7, n = i & 127;
            float acc = 0.f;
            for (int c = 0; c < 64; ++c)
                acc += g_sh[0][c] * w1[(k * 64 + c) * 128 + n];
            g_tb1f[i] = acc;
        }
    } else if (b < NB_F0 + NB_W1 + NB_TBF + NB_MI) {
        if (tid < 32)              ((__half2*)(g_f0h + NV * CA))[tid] = __half2half2(__ushort_as_half(0));
        if (tid >= 32 && tid < 96) ((__half2*)(g_h1h + NV * CB))[tid - 32] = __half2half2(__ushort_as_half(0));
    } else {
        int j = (b - NB_F0 - NB_W1 - NB_TBF - NB_MI) * 256 + tid;
        if (j < KOFF * NV) {
            int s = sidx[j];
            if (s < NV) {
                int k = j / NV;
                g_p2t[s * 32 + k] = (j - k * NV) + 1;
            }
        }
    }
}

// ---------------- prep2 ----------------
#define NB_W2  1728
#define NB_WN  32
__global__ void k_prep2(const float* __restrict__ w2, const float* __restrict__ wnin) {
    const int b = blockIdx.x;
    const int tid = threadIdx.x;
    if (b < NB_W2) {
        int i = b * 256 + tid;
        int k = i >> 14;
        int rem = i & 16383;
        int n = rem >> 7, c = rem & 127;
        g_w2h[i] = __float2half_rn(g_sc[1][c] * w2[(k * 128 + c) * 128 + n]);
    } else if (b < NB_W2 + NB_TBF) {
        int i = (b - NB_W2) * 256 + tid;
        if (i < KOFF * 128) {
            int k = i >> 7, n = i & 127;
            float acc = 0.f;
            for (int c = 0; c < 128; ++c)
                acc += g_sh[1][c] * w2[(k * 128 + c) * 128 + n];
            g_tb2f[i] = acc;
        }
    } else {
        int i = (b - NB_W2 - NB_TBF) * 256 + tid;
        int n = i >> 6, c = i & 63;
        g_wnh[i] = __float2half_rn(wnin[c * 128 + n]);
    }
}

// ---------------- compact per-k GEMM over valid slots ----------------
// HACC: fp16 accumulators (2x rate if HW supports), else fp32 accumulators.
template <int CIN, bool HACC>
__global__ void __launch_bounds__(256, 2)
k_convc(const __half* __restrict__ src, const __half* __restrict__ wt,
        const float* __restrict__ tbf, const int* __restrict__ gidx,
        const int* __restrict__ sidx, __half* __restrict__ temp) {
    const int kk   = blockIdx.x / TIL;
    const int tile = blockIdx.x - kk * TIL;
    if (sidx[kk * NV + tile * 128] >= NV) return;

    extern __shared__ __align__(16) char smraw[];
    constexpr int NCH = CIN / 64;
    float* sTB = (float*)(smraw + NCH * 32768);
    const uint32_t tile0 = smem_u32(smraw);

    const int tid  = threadIdx.x;
    const int lane = tid & 31;
    const int wid  = tid >> 5;
    const int g    = lane >> 2;
    const int tig  = lane & 3;
    const int warpRow = (wid & 3) * 32;
    const int warpCol = (wid >> 2) * 64;
    const int lr  = tid >> 3;
    const int sub = tid & 7;

    if (tid < 128) sTB[tid] = tbf[kk * 128 + tid];

    #pragma unroll
    for (int c = 0; c < NCH; ++c) {
        const uint32_t aB = tile0 + (uint32_t)c * 32768u;
        const uint32_t bB = aB + 16384u;
        #pragma unroll
        for (int j = 0; j < 4; ++j) {
            int r = lr + j * 32;
            int slot = tile * 128 + r;
            int gg = (slot < NV) ? gidx[kk * NV + slot] : NV;
            uint32_t off = (uint32_t)((r << 7) + ((sub ^ (r & 7)) << 4));
            cpa16(aB + off, src + (size_t)gg * CIN + c * 64 + sub * 8);
        }
        const __half* bs = wt + ((size_t)kk * 128) * CIN + c * 64;
        #pragma unroll
        for (int j = 0; j < 4; ++j) {
            int n = lr + j * 32;
            uint32_t off = (uint32_t)((n << 7) + ((sub ^ (n & 7)) << 4));
            cpa16(bB + off, bs + (size_t)n * CIN + sub * 8);
        }
        cpa_commit();
    }

    float    facc[2][8][4];
    uint32_t hacc[2][8][2];
    #pragma unroll
    for (int mt = 0; mt < 2; ++mt)
        #pragma unroll
        for (int nt = 0; nt < 8; ++nt) {
            if (HACC) { hacc[mt][nt][0] = 0u; hacc[mt][nt][1] = 0u; }
            else {
                #pragma unroll
                for (int q = 0; q < 4; ++q) facc[mt][nt][q] = 0.f;
            }
        }

    const int s7 = lane & 7;
    const int rowA = warpRow + s7 + ((lane >> 3) & 1) * 8;
    const int uA   = lane >> 4;
    const int rowB = warpCol + s7 + (lane >> 4) * 8;
    const int uB   = (lane >> 3) & 1;

    #pragma unroll
    for (int c = 0; c < NCH; ++c) {
        if (NCH == 2 && c == 0) cpa_wait1(); else cpa_wait0();
        __syncthreads();
        const uint32_t aB = tile0 + (uint32_t)c * 32768u;
        const uint32_t bB = aB + 16384u;
        const uint32_t pa0 = aB + ((uint32_t)rowA << 7);
        const uint32_t pa1 = aB + ((uint32_t)(rowA + 16) << 7);
        #pragma unroll
        for (int ks = 0; ks < 4; ++ks) {
            const int u0 = ks * 2;
            uint32_t a[2][4];
            const uint32_t aoff = (uint32_t)(((u0 + uA) ^ s7) << 4);
            ldsm4(a[0], pa0 + aoff);
            ldsm4(a[1], pa1 + aoff);
            const uint32_t boff = (uint32_t)(((u0 + uB) ^ s7) << 4);
            #pragma unroll
            for (int p = 0; p < 4; ++p) {
                uint32_t bfr[4];
                ldsm4(bfr, bB + ((uint32_t)(rowB + p * 16) << 7) + boff);
                if (HACC) {
                    mma16h(hacc[0][2 * p],     a[0], &bfr[0]);
                    mma16h(hacc[0][2 * p + 1], a[0], &bfr[2]);
                    mma16h(hacc[1][2 * p],     a[1], &bfr[0]);
                    mma16h(hacc[1][2 * p + 1], a[1], &bfr[2]);
                } else {
                    mma16(facc[0][2 * p],     a[0], &bfr[0]);
                    mma16(facc[0][2 * p + 1], a[0], &bfr[2]);
                    mma16(facc[1][2 * p],     a[1], &bfr[0]);
                    mma16(facc[1][2 * p + 1], a[1], &bfr[2]);
                }
            }
        }
    }

    #pragma unroll
    for (int mt = 0; mt < 2; ++mt) {
        int slot0 = tile * 128 + warpRow + mt * 16 + g;
        #pragma unroll
        for (int nt = 0; nt < 8; ++nt) {
            int col = warpCol + nt * 8 + 2 * tig;
            float t0 = sTB[col], t1 = sTB[col + 1];
            float c0, c1, c2, c3;
            if (HACC) {
                float2 x = __half22float2(*(__half2*)&hacc[mt][nt][0]);
                float2 y = __half22float2(*(__half2*)&hacc[mt][nt][1]);
                c0 = x.x; c1 = x.y; c2 = y.x; c3 = y.y;
            } else {
                c0 = facc[mt][nt][0]; c1 = facc[mt][nt][1];
                c2 = facc[mt][nt][2]; c3 = facc[mt][nt][3];
            }
            __half2 v0 = __floats2half2_rn(c0 + t0, c1 + t1);
            __half2 v1 = __floats2half2_rn(c2 + t0, c3 + t1);
            stcs32(temp + ((size_t)kk * NPAD + slot0) * 128 + col,     *(uint32_t*)&v0);
            stcs32(temp + ((size_t)kk * NPAD + slot0 + 8) * 128 + col, *(uint32_t*)&v1);
        }
    }
}

// ---------------- dense skip GEMM: base2h = f0h @ w_nin (fp16) ----------------
__global__ void __launch_bounds__(256, 2)
k_base2(const __half* __restrict__ src, const __half* __restrict__ wnh,
        __half* __restrict__ baseh) {
    extern __shared__ __align__(16) char smraw[];
    const uint32_t tile0 = smem_u32(smraw);
    const int tid  = threadIdx.x;
    const int lane = tid & 31;
    const int wid  = tid >> 5;
    const int g    = lane >> 2;
    const int tig  = lane & 3;
    const int tile = blockIdx.x;
    const int warpRow = (wid & 3) * 32;
    const int warpCol = (wid >> 2) * 64;
    const int lr  = tid >> 3;
    const int sub = tid & 7;

    const uint32_t aB = tile0, bB = tile0 + 16384u;
    #pragma unroll
    for (int j = 0; j < 4; ++j) {
        int r = lr + j * 32;
        int row = tile * 128 + r;
        int gg = (row < NV) ? row : NV;
        uint32_t off = (uint32_t)((r << 7) + ((sub ^ (r & 7)) << 4));
        cpa16(aB + off, src + (size_t)gg * 64 + sub * 8);
    }
    #pragma unroll
    for (int j = 0; j < 4; ++j) {
        int n = lr + j * 32;
        uint32_t off = (uint32_t)((n << 7) + ((sub ^ (n & 7)) << 4));
        cpa16(bB + off, wnh + (size_t)n * 64 + sub * 8);
    }
    cpa_commit();
    cpa_wait0();
    __syncthreads();

    float acc[2][8][4];
    #pragma unroll
    for (int mt = 0; mt < 2; ++mt)
        #pragma unroll
        for (int nt = 0; nt < 8; ++nt)
            #pragma unroll
            for (int q = 0; q < 4; ++q) acc[mt][nt][q] = 0.f;

    const int s7 = lane & 7;
    const int rowA = warpRow + s7 + ((lane >> 3) & 1) * 8;
    const int uA   = lane >> 4;
    const int rowB = warpCol + s7 + (lane >> 4) * 8;
    const int uB   = (lane >> 3) & 1;
    const uint32_t pa0 = aB + ((uint32_t)rowA << 7);
    const uint32_t pa1 = aB + ((uint32_t)(rowA + 16) << 7);

    #pragma unroll
    for (int ks = 0; ks < 4; ++ks) {
        const int u0 = ks * 2;
        uint32_t a[2][4];
        const uint32_t aoff = (uint32_t)(((u0 + uA) ^ s7) << 4);
        ldsm4(a[0], pa0 + aoff);
        ldsm4(a[1], pa1 + aoff);
        const uint32_t boff = (uint32_t)(((u0 + uB) ^ s7) << 4);
        #pragma unroll
        for (int p = 0; p < 4; ++p) {
            uint32_t bfr[4];
            ldsm4(bfr, bB + ((uint32_t)(rowB + p * 16) << 7) + boff);
            mma16(acc[0][2 * p],     a[0], &bfr[0]);
            mma16(acc[0][2 * p + 1], a[0], &bfr[2]);
            mma16(acc[1][2 * p],     a[1], &bfr[0]);
            mma16(acc[1][2 * p + 1], a[1], &bfr[2]);
        }
    }

    #pragma unroll
    for (int mt = 0; mt < 2; ++mt) {
        int r0 = tile * 128 + warpRow + mt * 16 + g;
        #pragma unroll
        for (int nt = 0; nt < 8; ++nt) {
            int col = warpCol + nt * 8 + 2 * tig;
            __half2 v0 = __floats2half2_rn(acc[mt][nt][0], acc[mt][nt][1]);
            __half2 v1 = __floats2half2_rn(acc[mt][nt][2], acc[mt][nt][3]);
            *(__half2*)(baseh + (size_t)r0 * 128 + col)       = v0;
            *(__half2*)(baseh + (size_t)(r0 + 8) * 128 + col) = v1;
        }
    }
}

// ---------------- reduce1 + BN2 stats fused ----------------
// grid = NBLK blocks x 256 thr. Warp gw handles rows gw, gw+2048, ...;
// lane owns cols [4*lane, 4*lane+3]. Per-block channel sums -> g_psum/g_psq.
__global__ void __launch_bounds__(256)
k_reduce1bn(const __half* __restrict__ temp, __half* __restrict__ dst) {
    const int lane = threadIdx.x & 31;
    const int w    = threadIdx.x >> 5;
    const int gw   = blockIdx.x * 8 + w;

    float s0 = 0.f, s1 = 0.f, s2 = 0.f, s3 = 0.f;
    float q0 = 0.f, q1 = 0.f, q2 = 0.f, q3 = 0.f;

    for (int i = gw; i < NV; i += NBLK * 8) {
        int myp = g_p2t[i * 32 + lane];
        float a0 = 0.f, a1 = 0.f, a2 = 0.f, a3 = 0.f;
        #pragma unroll
        for (int k = 0; k < KOFF; ++k) {
            int sp = __shfl_sync(0xffffffffu, myp, k);
            if (sp) {
                uint2 v = ldcs64(temp + ((size_t)k * NPAD + (sp - 1)) * 128 + lane * 4);
                float2 x = __half22float2(*(__half2*)&v.x);
                float2 y = __half22float2(*(__half2*)&v.y);
                a0 += x.x; a1 += x.y; a2 += y.x; a3 += y.y;
            }
        }
        __half2* o = (__half2*)(dst + (size_t)i * 128) + lane * 2;
        o[0] = __floats2half2_rn(a0, a1);
        o[1] = __floats2half2_rn(a2, a3);
        // accumulate BN stats on the rounded fp16 values (matches what conv2 sees)
        float2 r0 = __half22float2(o[0]);
        float2 r1 = __half22float2(o[1]);
        s0 += r0.x; s1 += r0.y; s2 += r1.x; s3 += r1.y;
        q0 += r0.x * r0.x; q1 += r0.y * r0.y; q2 += r1.x * r1.x; q3 += r1.y * r1.y;
    }

    __shared__ float sh[8 * 128];
    const int cbase = lane * 4;
    sh[w * 128 + cbase]     = s0;
    sh[w * 128 + cbase + 1] = s1;
    sh[w * 128 + cbase + 2] = s2;
    sh[w * 128 + cbase + 3] = s3;
    __syncthreads();
    if (threadIdx.x < 128) {
        float a = 0.f;
        #pragma unroll
        for (int j = 0; j < 8; ++j) a += sh[j * 128 + threadIdx.x];
        g_psum[blockIdx.x * 128 + threadIdx.x] = a;
    }
    __syncthreads();
    sh[w * 128 + cbase]     = q0;
    sh[w * 128 + cbase + 1] = q1;
    sh[w * 128 + cbase + 2] = q2;
    sh[w * 128 + cbase + 3] = q3;
    __syncthreads();
    if (threadIdx.x < 128) {
        float a = 0.f;
        #pragma unroll
        for (int j = 0; j < 8; ++j) a += sh[j * 128 + threadIdx.x];
        g_psq[blockIdx.x * 128 + threadIdx.x] = a;
    }
}

// ---------------- final reduce ----------------
__global__ void __launch_bounds__(256)
k_reduce2(const __half* __restrict__ temp, const __half* __restrict__ baseh,
          float* __restrict__ dst) {
    const int lane = threadIdx.x & 31;
    const int w    = threadIdx.x >> 5;
    const int i    = blockIdx.x * 8 + w;

    int myp = g_p2t[i * 32 + lane];
    uint2 b = ldcs64(baseh + (size_t)i * 128 + lane * 4);
    float2 b0 = __half22float2(*(__half2*)&b.x);
    float2 b1 = __half22float2(*(__half2*)&b.y);
    float a0 = b0.x, a1 = b0.y, a2 = b1.x, a3 = b1.y;
    #pragma unroll
    for (int k = 0; k < KOFF; ++k) {
        int sp = __shfl_sync(0xffffffffu, myp, k);
        if (sp) {
            uint2 v = ldcs64(temp + ((size_t)k * NPAD + (sp - 1)) * 128 + lane * 4);
            float2 x = __half22float2(*(__half2*)&v.x);
            float2 y = __half22float2(*(__half2*)&v.y);
            a0 += x.x; a1 += x.y; a2 += y.x; a3 += y.y;
        }
    }
    ((float4*)dst)[(size_t)i * 32 + lane] = make_float4(a0, a1, a2, a3);
}

// ---------------- launch ----------------
extern "C" void kernel_launch(void* const* d_in, const int* in_sizes, int n_in,
                              void* d_out, int out_size) {
    const float* feats     = (const float*)d_in[0];
    const float* w1        = (const float*)d_in[1];
    const float* w2        = (const float*)d_in[2];
    const float* w_nin     = (const float*)d_in[3];
    const float* bn1_gamma = (const float*)d_in[4];
    const float* bn1_beta  = (const float*)d_in[5];
    const float* bn2_gamma = (const float*)d_in[6];
    const float* bn2_beta  = (const float*)d_in[7];
    const int*   gidx      = (const int*)d_in[8];
    const int*   sidx      = (const int*)d_in[9];
    float*       out       = (float*)d_out;

    const int sm1 = 1 * 32768 + 512;
    const int sm2 = 2 * 32768 + 512;
    const int smb = 32768;
    cudaFuncSetAttribute(k_convc<CA, true >, cudaFuncAttributeMaxDynamicSharedMemorySize, sm1);
    cudaFuncSetAttribute(k_convc<CB, false>, cudaFuncAttributeMaxDynamicSharedMemorySize, sm2);
    cudaFuncSetAttribute(k_base2,            cudaFuncAttributeMaxDynamicSharedMemorySize, smb);

    __half *f0h, *h1h, *w1h, *w2h, *wnh, *temp, *baseh;
    float  *tb1f, *tb2f;
    cudaGetSymbolAddress((void**)&f0h,   g_f0h);
    cudaGetSymbolAddress((void**)&h1h,   g_h1h);
    cudaGetSymbolAddress((void**)&w1h,   g_w1h);
    cudaGetSymbolAddress((void**)&w2h,   g_w2h);
    cudaGetSymbolAddress((void**)&wnh,   g_wnh);
    cudaGetSymbolAddress((void**)&temp,  g_temp);
    cudaGetSymbolAddress((void**)&tb1f,  g_tb1f);
    cudaGetSymbolAddress((void**)&tb2f,  g_tb2f);
    cudaGetSymbolAddress((void**)&baseh, g_base2h);

    // 1-2: BN1 stats (+ p2t zero)
    k_bn_partial<CA><<<NBLK, 256>>>(feats);
    k_bn_finalize<CA, 0><<<1, 4 * CA>>>(bn1_gamma, bn1_beta);
    // 3: prep1
    k_prep1<<<NB_F0 + NB_W1 + NB_TBF + NB_MI + NB_MAP, 256>>>(feats, w1, sidx);
    // 4: conv1 compact GEMM, fp16 accumulators (profiled slot)
    k_convc<CA, true><<<KOFF * TIL, 256, sm1>>>(f0h, w1h, tb1f, gidx, sidx, temp);
    // 5: reduce1 + BN2 stats fused -> h1h + g_psum/g_psq
    k_reduce1bn<<<NBLK, 256>>>(temp, h1h);
    // 6: BN2 finalize
    k_bn_finalize<CB, 1><<<1, 4 * CB>>>(bn2_gamma, bn2_beta);
    // 7: prep2
    k_prep2<<<NB_W2 + NB_TBF + NB_WN, 256>>>(w2, w_nin);
    // 8: skip GEMM (fp16 base)
    k_base2<<<TIL, 256, smb>>>(f0h, wnh, baseh);
    // 9: conv2 compact GEMM (fp32 accumulators)
    k_convc<CB, false><<<KOFF * TIL, 256, sm2>>>(h1h, w2h, tb2f, gidx, sidx, temp);
    // 10: final reduce -> out
    k_reduce2<<<NV / 8, 256>>>(temp, baseh, out);
}

// round 15
// speedup vs baseline: 1.4209x; 1.4209x over previous
#include <cuda_runtime.h>
#include <cuda_fp16.h>
#include <cstdint>

#define NV   200000
#define NPAD 200064
#define TIL  1563
#define KOFF 27
#define CA   64
#define CB   128
#define NBLK 256
#define EPSF 1e-5f

// ---------------- device scratch ----------------
__device__ __half g_f0h[(NV + 1) * CA];
__device__ __half g_h1h[(NV + 1) * CB];
__device__ __half g_temp[(size_t)KOFF * NPAD * 128];
__device__ int    g_p2t[NPAD * 32];
__device__ __half g_base2h[(size_t)NPAD * 128];
__device__ __half g_w1h[KOFF * CB * CA];
__device__ __half g_w2h[KOFF * CB * CB];
__device__ float  g_tb1f[KOFF * 128];
__device__ float  g_tb2f[KOFF * 128];
__device__ __half g_wnh[CB * 64];
__device__ float  g_psum[NBLK * CB];
__device__ float  g_psq [NBLK * CB];
__device__ float  g_sc[2][CB];
__device__ float  g_sh[2][CB];

// ---------------- helpers ----------------
__device__ __forceinline__ uint32_t smem_u32(const void* p) {
    uint32_t a;
    asm("{ .reg .u64 t; cvta.to.shared.u64 t, %1; cvt.u32.u64 %0, t; }" : "=r"(a) : "l"(p));
    return a;
}
__device__ __forceinline__ void cpa16(uint32_t s, const void* g) {
    asm volatile("cp.async.cg.shared.global [%0], [%1], 16;" :: "r"(s), "l"(g));
}
__device__ __forceinline__ void cpa_commit() { asm volatile("cp.async.commit_group;" ::: "memory"); }
__device__ __forceinline__ void cpa_wait1()  { asm volatile("cp.async.wait_group 1;" ::: "memory"); }
__device__ __forceinline__ void cpa_wait0()  { asm volatile("cp.async.wait_group 0;" ::: "memory"); }
__device__ __forceinline__ void ldsm4(uint32_t* d, uint32_t addr) {
    asm volatile("ldmatrix.sync.aligned.m8n8.x4.shared.b16 {%0,%1,%2,%3}, [%4];"
                 : "=r"(d[0]), "=r"(d[1]), "=r"(d[2]), "=r"(d[3]) : "r"(addr));
}
__device__ __forceinline__ void mma16(float* c, const uint32_t* a, const uint32_t* b) {
    asm volatile(
        "mma.sync.aligned.m16n8k16.row.col.f32.f16.f16.f32 "
        "{%0,%1,%2,%3}, {%4,%5,%6,%7}, {%8,%9}, {%0,%1,%2,%3};"
        : "+f"(c[0]), "+f"(c[1]), "+f"(c[2]), "+f"(c[3])
        : "r"(a[0]), "r"(a[1]), "r"(a[2]), "r"(a[3]), "r"(b[0]), "r"(b[1]));
}
__device__ __forceinline__ void mma16h(uint32_t* c, const uint32_t* a, const uint32_t* b) {
    asm volatile(
        "mma.sync.aligned.m16n8k16.row.col.f16.f16.f16.f16 "
        "{%0,%1}, {%2,%3,%4,%5}, {%6,%7}, {%0,%1};"
        : "+r"(c[0]), "+r"(c[1])
        : "r"(a[0]), "r"(a[1]), "r"(a[2]), "r"(a[3]), "r"(b[0]), "r"(b[1]));
}
__device__ __forceinline__ void stcs32(void* p, uint32_t v) {
    asm volatile("st.global.cs.b32 [%0], %1;" :: "l"(p), "r"(v) : "memory");
}
__device__ __forceinline__ uint2 ldcs64(const void* p) {
    uint2 r;
    asm volatile("ld.global.cs.v2.b32 {%0,%1}, [%2];" : "=r"(r.x), "=r"(r.y) : "l"(p));
    return r;
}

// ---------------- BN stats: fp32 feats (+ zero p2t) ----------------
template <int C>
__global__ void k_bn_partial(const float* __restrict__ x) {
    const int tid = threadIdx.x;
    if (C == CA) {
        const int n4 = NPAD * 32 / 4;
        for (int i = blockIdx.x * 256 + tid; i < n4; i += NBLK * 256)
            ((int4*)g_p2t)[i] = make_int4(0, 0, 0, 0);
    }
    const int C4 = C / 4;
    float4 s = make_float4(0.f, 0.f, 0.f, 0.f);
    float4 q = make_float4(0.f, 0.f, 0.f, 0.f);
    const int tot = NV * C4;
    for (int i = blockIdx.x * 256 + tid; i < tot; i += NBLK * 256) {
        float4 v = ((const float4*)x)[i];
        s.x += v.x; s.y += v.y; s.z += v.z; s.w += v.w;
        q.x += v.x * v.x; q.y += v.y * v.y; q.z += v.z * v.z; q.w += v.w * v.w;
    }
    __shared__ float4 sh[256];
    sh[tid] = s;
    __syncthreads();
    if (tid < C4) {
        float4 a = sh[tid];
        for (int o = C4; o < 256; o += C4) {
            float4 b = sh[tid + o];
            a.x += b.x; a.y += b.y; a.z += b.z; a.w += b.w;
        }
        ((float4*)(g_psum + blockIdx.x * C))[tid] = a;
    }
    __syncthreads();
    sh[tid] = q;
    __syncthreads();
    if (tid < C4) {
        float4 a = sh[tid];
        for (int o = C4; o < 256; o += C4) {
            float4 b = sh[tid + o];
            a.x += b.x; a.y += b.y; a.z += b.z; a.w += b.w;
        }
        ((float4*)(g_psq + blockIdx.x * C))[tid] = a;
    }
}

// ---------------- BN stats: fp16 input (h1h), C = 128 ----------------
__global__ void k_bn_partial_h(const __half* __restrict__ x) {
    float s[8], q[8];
    #pragma unroll
    for (int t = 0; t < 8; ++t) { s[t] = 0.f; q[t] = 0.f; }
    const int tid = threadIdx.x;
    const int tot = NV * 16;
    for (int i = blockIdx.x * 256 + tid; i < tot; i += NBLK * 256) {
        uint4 v = ((const uint4*)x)[i];
        const uint32_t u[4] = {v.x, v.y, v.z, v.w};
        #pragma unroll
        for (int p = 0; p < 4; ++p) {
            float2 f = __half22float2(*(const __half2*)&u[p]);
            s[2 * p] += f.x; s[2 * p + 1] += f.y;
            q[2 * p] += f.x * f.x; q[2 * p + 1] += f.y * f.y;
        }
    }
    __shared__ float sh[256 * 8];
    #pragma unroll
    for (int t = 0; t < 8; ++t) sh[tid * 8 + t] = s[t];
    __syncthreads();
    if (tid < 128) {
        int cb = tid >> 3, ci = tid & 7;
        float a = 0.f;
        #pragma unroll
        for (int j = 0; j < 16; ++j) a += sh[(cb + 16 * j) * 8 + ci];
        g_psum[blockIdx.x * 128 + tid] = a;
    }
    __syncthreads();
    #pragma unroll
    for (int t = 0; t < 8; ++t) sh[tid * 8 + t] = q[t];
    __syncthreads();
    if (tid < 128) {
        int cb = tid >> 3, ci = tid & 7;
        float a = 0.f;
        #pragma unroll
        for (int j = 0; j < 16; ++j) a += sh[(cb + 16 * j) * 8 + ci];
        g_psq[blockIdx.x * 128 + tid] = a;
    }
}

template <int C, int IDX>
__global__ void k_bn_finalize(const float* __restrict__ gamma, const float* __restrict__ beta) {
    const int tid = threadIdx.x;   // blockDim = 4*C
    const int c = tid % C;
    const int qd = tid / C;
    float s = 0.f, s2 = 0.f;
    #pragma unroll 8
    for (int b = qd * (NBLK / 4); b < (qd + 1) * (NBLK / 4); ++b) {
        s  += g_psum[b * C + c];
        s2 += g_psq [b * C + c];
    }
    __shared__ float sha[4 * CB], shb[4 * CB];
    sha[tid] = s; shb[tid] = s2;
    __syncthreads();
    if (qd == 0) {
        s  = sha[c] + sha[C + c] + sha[2 * C + c] + sha[3 * C + c];
        s2 = shb[c] + shb[C + c] + shb[2 * C + c] + shb[3 * C + c];
        float mean = s / (float)NV;
        float var  = s2 / (float)NV - mean * mean;
        float a = rsqrtf(var + EPSF) * gamma[c];
        g_sc[IDX][c] = a;
        g_sh[IDX][c] = beta[c] - mean * a;
    }
}

// ---------------- prep1 ----------------
#define NB_F0  12500
#define NB_W1  864
#define NB_TBF 14
#define NB_MI  1
#define NB_MAP 21094
__global__ void k_prep1(const float* __restrict__ feats, const float* __restrict__ w1,
                        const int* __restrict__ sidx) {
    const int b = blockIdx.x;
    const int tid = threadIdx.x;
    if (b < NB_F0) {
        int i = b * 256 + tid;
        float4 v = ((const float4*)feats)[i];
        ((__half2*)g_f0h)[2 * i]     = __floats2half2_rn(v.x, v.y);
        ((__half2*)g_f0h)[2 * i + 1] = __floats2half2_rn(v.z, v.w);
    } else if (b < NB_F0 + NB_W1) {
        int i = (b - NB_F0) * 256 + tid;
        int k = i >> 13;
        int rem = i & 8191;
        int n = rem >> 6, c = rem & 63;
        g_w1h[i] = __float2half_rn(g_sc[0][c] * w1[(k * 64 + c) * 128 + n]);
    } else if (b < NB_F0 + NB_W1 + NB_TBF) {
        int i = (b - NB_F0 - NB_W1) * 256 + tid;
        if (i < KOFF * 128) {
            int k = i >> 7, n = i & 127;
            float acc = 0.f;
            for (int c = 0; c < 64; ++c)
                acc += g_sh[0][c] * w1[(k * 64 + c) * 128 + n];
            g_tb1f[i] = acc;
        }
    } else if (b < NB_F0 + NB_W1 + NB_TBF + NB_MI) {
        if (tid < 32)              ((__half2*)(g_f0h + NV * CA))[tid] = __half2half2(__ushort_as_half(0));
        if (tid >= 32 && tid < 96) ((__half2*)(g_h1h + NV * CB))[tid - 32] = __half2half2(__ushort_as_half(0));
    } else {
        int j = (b - NB_F0 - NB_W1 - NB_TBF - NB_MI) * 256 + tid;
        if (j < KOFF * NV) {
            int s = sidx[j];
            if (s < NV) {
                int k = j / NV;
                g_p2t[s * 32 + k] = (j - k * NV) + 1;
            }
        }
    }
}

// ---------------- prep2 ----------------
#define NB_W2  1728
#define NB_WN  32
__global__ void k_prep2(const float* __restrict__ w2, const float* __restrict__ wnin) {
    const int b = blockIdx.x;
    const int tid = threadIdx.x;
    if (b < NB_W2) {
        int i = b * 256 + tid;
        int k = i >> 14;
        int rem = i & 16383;
        int n = rem >> 7, c = rem & 127;
        g_w2h[i] = __float2half_rn(g_sc[1][c] * w2[(k * 128 + c) * 128 + n]);
    } else if (b < NB_W2 + NB_TBF) {
        int i = (b - NB_W2) * 256 + tid;
        if (i < KOFF * 128) {
            int k = i >> 7, n = i & 127;
            float acc = 0.f;
            for (int c = 0; c < 128; ++c)
                acc += g_sh[1][c] * w2[(k * 128 + c) * 128 + n];
            g_tb2f[i] = acc;
        }
    } else {
        int i = (b - NB_W2 - NB_TBF) * 256 + tid;
        int n = i >> 6, c = i & 63;
        g_wnh[i] = __float2half_rn(wnin[c * 128 + n]);
    }
}

// ---------------- compact per-k GEMM over valid slots (fp16 accumulators) ----
template <int CIN>
__global__ void __launch_bounds__(256, 2)
k_convc(const __half* __restrict__ src, const __half* __restrict__ wt,
        const float* __restrict__ tbf, const int* __restrict__ gidx,
        const int* __restrict__ sidx, __half* __restrict__ temp) {
    const int kk   = blockIdx.x / TIL;
    const int tile = blockIdx.x - kk * TIL;
    if (sidx[kk * NV + tile * 128] >= NV) return;

    extern __shared__ __align__(16) char smraw[];
    constexpr int NCH = CIN / 64;
    float* sTB = (float*)(smraw + NCH * 32768);
    const uint32_t tile0 = smem_u32(smraw);

    const int tid  = threadIdx.x;
    const int lane = tid & 31;
    const int wid  = tid >> 5;
    const int g    = lane >> 2;
    const int tig  = lane & 3;
    const int warpRow = (wid & 3) * 32;
    const int warpCol = (wid >> 2) * 64;
    const int lr  = tid >> 3;
    const int sub = tid & 7;

    if (tid < 128) sTB[tid] = tbf[kk * 128 + tid];

    #pragma unroll
    for (int c = 0; c < NCH; ++c) {
        const uint32_t aB = tile0 + (uint32_t)c * 32768u;
        const uint32_t bB = aB + 16384u;
        #pragma unroll
        for (int j = 0; j < 4; ++j) {
            int r = lr + j * 32;
            int slot = tile * 128 + r;
            int gg = (slot < NV) ? gidx[kk * NV + slot] : NV;
            uint32_t off = (uint32_t)((r << 7) + ((sub ^ (r & 7)) << 4));
            cpa16(aB + off, src + (size_t)gg * CIN + c * 64 + sub * 8);
        }
        const __half* bs = wt + ((size_t)kk * 128) * CIN + c * 64;
        #pragma unroll
        for (int j = 0; j < 4; ++j) {
            int n = lr + j * 32;
            uint32_t off = (uint32_t)((n << 7) + ((sub ^ (n & 7)) << 4));
            cpa16(bB + off, bs + (size_t)n * CIN + sub * 8);
        }
        cpa_commit();
    }

    uint32_t hacc[2][8][2];
    #pragma unroll
    for (int mt = 0; mt < 2; ++mt)
        #pragma unroll
        for (int nt = 0; nt < 8; ++nt) {
            hacc[mt][nt][0] = 0u; hacc[mt][nt][1] = 0u;
        }

    const int s7 = lane & 7;
    const int rowA = warpRow + s7 + ((lane >> 3) & 1) * 8;
    const int uA   = lane >> 4;
    const int rowB = warpCol + s7 + (lane >> 4) * 8;
    const int uB   = (lane >> 3) & 1;

    #pragma unroll
    for (int c = 0; c < NCH; ++c) {
        if (NCH == 2 && c == 0) cpa_wait1(); else cpa_wait0();
        __syncthreads();
        const uint32_t aB = tile0 + (uint32_t)c * 32768u;
        const uint32_t bB = aB + 16384u;
        const uint32_t pa0 = aB + ((uint32_t)rowA << 7);
        const uint32_t pa1 = aB + ((uint32_t)(rowA + 16) << 7);
        #pragma unroll
        for (int ks = 0; ks < 4; ++ks) {
            const int u0 = ks * 2;
            uint32_t a[2][4];
            const uint32_t aoff = (uint32_t)(((u0 + uA) ^ s7) << 4);
            ldsm4(a[0], pa0 + aoff);
            ldsm4(a[1], pa1 + aoff);
            const uint32_t boff = (uint32_t)(((u0 + uB) ^ s7) << 4);
            #pragma unroll
            for (int p = 0; p < 4; ++p) {
                uint32_t bfr[4];
                ldsm4(bfr, bB + ((uint32_t)(rowB + p * 16) << 7) + boff);
                mma16h(hacc[0][2 * p],     a[0], &bfr[0]);
                mma16h(hacc[0][2 * p + 1], a[0], &bfr[2]);
                mma16h(hacc[1][2 * p],     a[1], &bfr[0]);
                mma16h(hacc[1][2 * p + 1], a[1], &bfr[2]);
            }
        }
    }

    #pragma unroll
    for (int mt = 0; mt < 2; ++mt) {
        int slot0 = tile * 128 + warpRow + mt * 16 + g;
        #pragma unroll
        for (int nt = 0; nt < 8; ++nt) {
            int col = warpCol + nt * 8 + 2 * tig;
            float t0 = sTB[col], t1 = sTB[col + 1];
            float2 x = __half22float2(*(__half2*)&hacc[mt][nt][0]);
            float2 y = __half22float2(*(__half2*)&hacc[mt][nt][1]);
            __half2 v0 = __floats2half2_rn(x.x + t0, x.y + t1);
            __half2 v1 = __floats2half2_rn(y.x + t0, y.y + t1);
            stcs32(temp + ((size_t)kk * NPAD + slot0) * 128 + col,     *(uint32_t*)&v0);
            stcs32(temp + ((size_t)kk * NPAD + slot0 + 8) * 128 + col, *(uint32_t*)&v1);
        }
    }
}

// ---------------- dense skip GEMM: base2h = f0h @ w_nin (fp16) ----------------
__global__ void __launch_bounds__(256, 2)
k_base2(const __half* __restrict__ src, const __half* __restrict__ wnh,
        __half* __restrict__ baseh) {
    extern __shared__ __align__(16) char smraw[];
    const uint32_t tile0 = smem_u32(smraw);
    const int tid  = threadIdx.x;
    const int lane = tid & 31;
    const int wid  = tid >> 5;
    const int g    = lane >> 2;
    const int tig  = lane & 3;
    const int tile = blockIdx.x;
    const int warpRow = (wid & 3) * 32;
    const int warpCol = (wid >> 2) * 64;
    const int lr  = tid >> 3;
    const int sub = tid & 7;

    const uint32_t aB = tile0, bB = tile0 + 16384u;
    #pragma unroll
    for (int j = 0; j < 4; ++j) {
        int r = lr + j * 32;
        int row = tile * 128 + r;
        int gg = (row < NV) ? row : NV;
        uint32_t off = (uint32_t)((r << 7) + ((sub ^ (r & 7)) << 4));
        cpa16(aB + off, src + (size_t)gg * 64 + sub * 8);
    }
    #pragma unroll
    for (int j = 0; j < 4; ++j) {
        int n = lr + j * 32;
        uint32_t off = (uint32_t)((n << 7) + ((sub ^ (n & 7)) << 4));
        cpa16(bB + off, wnh + (size_t)n * 64 + sub * 8);
    }
    cpa_commit();
    cpa_wait0();
    __syncthreads();

    float acc[2][8][4];
    #pragma unroll
    for (int mt = 0; mt < 2; ++mt)
        #pragma unroll
        for (int nt = 0; nt < 8; ++nt)
            #pragma unroll
            for (int q = 0; q < 4; ++q) acc[mt][nt][q] = 0.f;

    const int s7 = lane & 7;
    const int rowA = warpRow + s7 + ((lane >> 3) & 1) * 8;
    const int uA   = lane >> 4;
    const int rowB = warpCol + s7 + (lane >> 4) * 8;
    const int uB   = (lane >> 3) & 1;
    const uint32_t pa0 = aB + ((uint32_t)rowA << 7);
    const uint32_t pa1 = aB + ((uint32_t)(rowA + 16) << 7);

    #pragma unroll
    for (int ks = 0; ks < 4; ++ks) {
        const int u0 = ks * 2;
        uint32_t a[2][4];
        const uint32_t aoff = (uint32_t)(((u0 + uA) ^ s7) << 4);
        ldsm4(a[0], pa0 + aoff);
        ldsm4(a[1], pa1 + aoff);
        const uint32_t boff = (uint32_t)(((u0 + uB) ^ s7) << 4);
        #pragma unroll
        for (int p = 0; p < 4; ++p) {
            uint32_t bfr[4];
            ldsm4(bfr, bB + ((uint32_t)(rowB + p * 16) << 7) + boff);
            mma16(acc[0][2 * p],     a[0], &bfr[0]);
            mma16(acc[0][2 * p + 1], a[0], &bfr[2]);
            mma16(acc[1][2 * p],     a[1], &bfr[0]);
            mma16(acc[1][2 * p + 1], a[1], &bfr[2]);
        }
    }

    #pragma unroll
    for (int mt = 0; mt < 2; ++mt) {
        int r0 = tile * 128 + warpRow + mt * 16 + g;
        #pragma unroll
        for (int nt = 0; nt < 8; ++nt) {
            int col = warpCol + nt * 8 + 2 * tig;
            __half2 v0 = __floats2half2_rn(acc[mt][nt][0], acc[mt][nt][1]);
            __half2 v1 = __floats2half2_rn(acc[mt][nt][2], acc[mt][nt][3]);
            *(__half2*)(baseh + (size_t)r0 * 128 + col)       = v0;
            *(__half2*)(baseh + (size_t)(r0 + 8) * 128 + col) = v1;
        }
    }
}

// ---------------- gather-reduce (fully parallel, warp per row) ----------------
template <bool FINAL>
__global__ void __launch_bounds__(256)
k_reduce(const __half* __restrict__ temp, const __half* __restrict__ baseh,
         void* __restrict__ dstv) {
    const int lane = threadIdx.x & 31;
    const int w    = threadIdx.x >> 5;
    const int i    = blockIdx.x * 8 + w;

    int myp = g_p2t[i * 32 + lane];
    float a0, a1, a2, a3;
    if (FINAL) {
        uint2 b = ldcs64(baseh + (size_t)i * 128 + lane * 4);
        float2 b0 = __half22float2(*(__half2*)&b.x);
        float2 b1 = __half22float2(*(__half2*)&b.y);
        a0 = b0.x; a1 = b0.y; a2 = b1.x; a3 = b1.y;
    } else {
        a0 = a1 = a2 = a3 = 0.f;
    }
    #pragma unroll
    for (int k = 0; k < KOFF; ++k) {
        int sp = __shfl_sync(0xffffffffu, myp, k);
        if (sp) {
            uint2 v = ldcs64(temp + ((size_t)k * NPAD + (sp - 1)) * 128 + lane * 4);
            float2 x = __half22float2(*(__half2*)&v.x);
            float2 y = __half22float2(*(__half2*)&v.y);
            a0 += x.x; a1 += x.y; a2 += y.x; a3 += y.y;
        }
    }
    if (FINAL) {
        ((float4*)dstv)[(size_t)i * 32 + lane] = make_float4(a0, a1, a2, a3);
    } else {
        __half2* o = (__half2*)((__half*)dstv + (size_t)i * 128) + lane * 2;
        o[0] = __floats2half2_rn(a0, a1);
        o[1] = __floats2half2_rn(a2, a3);
    }
}

// ---------------- launch ----------------
extern "C" void kernel_launch(void* const* d_in, const int* in_sizes, int n_in,
                              void* d_out, int out_size) {
    const float* feats     = (const float*)d_in[0];
    const float* w1        = (const float*)d_in[1];
    const float* w2        = (const float*)d_in[2];
    const float* w_nin     = (const float*)d_in[3];
    const float* bn1_gamma = (const float*)d_in[4];
    const float* bn1_beta  = (const float*)d_in[5];
    const float* bn2_gamma = (const float*)d_in[6];
    const float* bn2_beta  = (const float*)d_in[7];
    const int*   gidx      = (const int*)d_in[8];
    const int*   sidx      = (const int*)d_in[9];
    float*       out       = (float*)d_out;

    const int sm1 = 1 * 32768 + 512;
    const int sm2 = 2 * 32768 + 512;
    const int smb = 32768;
    cudaFuncSetAttribute(k_convc<CA>, cudaFuncAttributeMaxDynamicSharedMemorySize, sm1);
    cudaFuncSetAttribute(k_convc<CB>, cudaFuncAttributeMaxDynamicSharedMemorySize, sm2);
    cudaFuncSetAttribute(k_base2,     cudaFuncAttributeMaxDynamicSharedMemorySize, smb);

    __half *f0h, *h1h, *w1h, *w2h, *wnh, *temp, *baseh;
    float  *tb1f, *tb2f;
    cudaGetSymbolAddress((void**)&f0h,   g_f0h);
    cudaGetSymbolAddress((void**)&h1h,   g_h1h);
    cudaGetSymbolAddress((void**)&w1h,   g_w1h);
    cudaGetSymbolAddress((void**)&w2h,   g_w2h);
    cudaGetSymbolAddress((void**)&wnh,   g_wnh);
    cudaGetSymbolAddress((void**)&temp,  g_temp);
    cudaGetSymbolAddress((void**)&tb1f,  g_tb1f);
    cudaGetSymbolAddress((void**)&tb2f,  g_tb2f);
    cudaGetSymbolAddress((void**)&baseh, g_base2h);

    // 1-2: BN1 stats (+ p2t zero)
    k_bn_partial<CA><<<NBLK, 256>>>(feats);
    k_bn_finalize<CA, 0><<<1, 4 * CA>>>(bn1_gamma, bn1_beta);
    // 3: prep1
    k_prep1<<<NB_F0 + NB_W1 + NB_TBF + NB_MI + NB_MAP, 256>>>(feats, w1, sidx);
    // 4: conv1 compact GEMM, fp16 acc (profiled slot)
    k_convc<CA><<<KOFF * TIL, 256, sm1>>>(f0h, w1h, tb1f, gidx, sidx, temp);
    // 5: reduce1 -> h1h (fully parallel)
    k_reduce<false><<<NV / 8, 256>>>(temp, nullptr, h1h);
    // 6-7: BN2 stats
    k_bn_partial_h<<<NBLK, 256>>>(h1h);
    k_bn_finalize<CB, 1><<<1, 4 * CB>>>(bn2_gamma, bn2_beta);
    // 8: prep2
    k_prep2<<<NB_W2 + NB_TBF + NB_WN, 256>>>(w2, w_nin);
    // 9: skip GEMM
    k_base2<<<TIL, 256, smb>>>(f0h, wnh, baseh);
    // 10: conv2 compact GEMM, fp16 acc
    k_convc<CB><<<KOFF * TIL, 256, sm2>>>(h1h, w2h, tb2f, gidx, sidx, temp);
    // 11: final reduce -> out
    k_reduce<true><<<NV / 8, 256>>>(temp, baseh, out);
}